// round 1
// baseline (speedup 1.0000x reference)
#include <cuda_runtime.h>
#include <cuda_bf16.h>

#define BB 32
#define NN 512
#define DD 256
#define NEG_INF -9e15f

// scratch: scores / alpha buffer [B,N,N] (device global: no allocation allowed)
__device__ float g_scores[(size_t)BB * NN * NN];

// ---------------------------------------------------------------------------
// K1: scores[b,i,j] = select(adj, leaky_relu( sum_d h[i,d]*a_k[d]*h[j,d] ))
// 64x64 tile per block, 256 threads, 4x4 micro-tile, 4 accumulators per pair.
// e_k += (hi*hj) * a_k[d]  -> 1 FMUL + 4 FFMA per (pair,d)
// ---------------------------------------------------------------------------
__global__ __launch_bounds__(256) void k_scores(
    const float* __restrict__ h, const int* __restrict__ adj,
    const float* __restrict__ a0, const float* __restrict__ a1,
    const float* __restrict__ a2, const float* __restrict__ a3)
{
    __shared__ float As[32][68];   // h_i chunk, transposed [dd][i]
    __shared__ float Bs[32][68];   // h_j chunk, transposed [dd][j]
    __shared__ float a_s[32][4];   // a_k chunk [dd][k]

    const int b  = blockIdx.z;
    const int i0 = blockIdx.y * 64;
    const int j0 = blockIdx.x * 64;
    const int t  = threadIdx.x;
    const int tx = t & 15;         // j group
    const int ty = t >> 4;         // i group

    const float* hb = h + (size_t)b * NN * DD;

    float acc0[4][4], acc1[4][4], acc2[4][4], acc3[4][4];
#pragma unroll
    for (int i = 0; i < 4; i++)
#pragma unroll
        for (int j = 0; j < 4; j++) {
            acc0[i][j] = 0.f; acc1[i][j] = 0.f;
            acc2[i][j] = 0.f; acc3[i][j] = 0.f;
        }

    for (int d0 = 0; d0 < DD; d0 += 32) {
#pragma unroll
        for (int r = t; r < 64 * 32; r += 256) {
            int i  = r >> 5;
            int dd = r & 31;
            As[dd][i] = hb[(size_t)(i0 + i) * DD + d0 + dd];
            Bs[dd][i] = hb[(size_t)(j0 + i) * DD + d0 + dd];
        }
        if (t < 128) {
            int k = t >> 5, dd = t & 31;
            const float* ap = (k == 0) ? a0 : (k == 1) ? a1 : (k == 2) ? a2 : a3;
            a_s[dd][k] = ap[d0 + dd];
        }
        __syncthreads();

#pragma unroll
        for (int dd = 0; dd < 32; dd++) {
            const float4 hi4 = *(const float4*)&As[dd][ty * 4];
            const float4 hj4 = *(const float4*)&Bs[dd][tx * 4];
            const float4 av  = *(const float4*)&a_s[dd][0];
            const float hi[4] = {hi4.x, hi4.y, hi4.z, hi4.w};
            const float hj[4] = {hj4.x, hj4.y, hj4.z, hj4.w};
#pragma unroll
            for (int i = 0; i < 4; i++)
#pragma unroll
                for (int j = 0; j < 4; j++) {
                    float p = hi[i] * hj[j];
                    acc0[i][j] += p * av.x;
                    acc1[i][j] += p * av.y;
                    acc2[i][j] += p * av.z;
                    acc3[i][j] += p * av.w;
                }
        }
        __syncthreads();
    }

    // epilogue: adj select + leaky relu + mask
#pragma unroll
    for (int i = 0; i < 4; i++) {
        const int gi = i0 + ty * 4 + i;
        const size_t rowoff = ((size_t)b * NN + gi) * NN + j0 + tx * 4;
        const int4 c4 = *(const int4*)&adj[rowoff];
        const int cc[4] = {c4.x, c4.y, c4.z, c4.w};
        float o[4];
#pragma unroll
        for (int j = 0; j < 4; j++) {
            const int c = cc[j];
            float e;
            if      (c == 1) e = acc0[i][j];
            else if (c == 2) e = acc1[i][j];
            else if (c == 3) e = acc2[i][j];
            else if (c == 4) e = acc3[i][j];
            else { o[j] = NEG_INF; continue; }
            o[j] = (e > 0.f) ? e : 0.2f * e;
        }
        *(float4*)&g_scores[rowoff] = make_float4(o[0], o[1], o[2], o[3]);
    }
}

// ---------------------------------------------------------------------------
// K2: row softmax in place. One warp per row of 512, 16 elems/lane.
// ---------------------------------------------------------------------------
__global__ __launch_bounds__(256) void k_softmax()
{
    const int warp = threadIdx.x >> 5;
    const int lane = threadIdx.x & 31;
    const size_t row = (size_t)blockIdx.x * 8 + warp;   // B*N rows
    float* p = g_scores + row * NN;

    float v[16];
#pragma unroll
    for (int q = 0; q < 16; q++) v[q] = p[q * 32 + lane];

    float m = v[0];
#pragma unroll
    for (int q = 1; q < 16; q++) m = fmaxf(m, v[q]);
#pragma unroll
    for (int o = 16; o > 0; o >>= 1) m = fmaxf(m, __shfl_xor_sync(0xffffffffu, m, o));

    float sum = 0.f;
#pragma unroll
    for (int q = 0; q < 16; q++) { v[q] = __expf(v[q] - m); sum += v[q]; }
#pragma unroll
    for (int o = 16; o > 0; o >>= 1) sum += __shfl_xor_sync(0xffffffffu, sum, o);

    const float inv = 1.f / sum;
#pragma unroll
    for (int q = 0; q < 16; q++) p[q * 32 + lane] = v[q] * inv;
}

// ---------------------------------------------------------------------------
// K3: out[b,i,d] = sum_j alpha[b,i,j] * h[b,j,d]. 64(i)x64(d) tile, k-chunk 32.
// ---------------------------------------------------------------------------
__global__ __launch_bounds__(256) void k_av(
    const float* __restrict__ h, float* __restrict__ out)
{
    __shared__ float As[32][68];  // alpha transposed [kk][i]
    __shared__ float Bs[32][68];  // h [kk][n]

    const int b  = blockIdx.z;
    const int i0 = blockIdx.y * 64;
    const int n0 = blockIdx.x * 64;
    const int t  = threadIdx.x;
    const int tx = t & 15;        // d group
    const int ty = t >> 4;        // i group

    const float* al = g_scores + (size_t)b * NN * NN;
    const float* hb = h + (size_t)b * NN * DD;

    float acc[4][4];
#pragma unroll
    for (int i = 0; i < 4; i++)
#pragma unroll
        for (int j = 0; j < 4; j++) acc[i][j] = 0.f;

    for (int k0 = 0; k0 < NN; k0 += 32) {
#pragma unroll
        for (int r = t; r < 64 * 32; r += 256) {
            int i = r >> 5, kk = r & 31;
            As[kk][i] = al[(size_t)(i0 + i) * NN + k0 + kk];
        }
#pragma unroll
        for (int r = t; r < 32 * 64; r += 256) {
            int kk = r >> 6, nn = r & 63;
            Bs[kk][nn] = hb[(size_t)(k0 + kk) * DD + n0 + nn];
        }
        __syncthreads();

#pragma unroll
        for (int kk = 0; kk < 32; kk++) {
            const float4 a4 = *(const float4*)&As[kk][ty * 4];
            const float4 b4 = *(const float4*)&Bs[kk][tx * 4];
            const float ai[4] = {a4.x, a4.y, a4.z, a4.w};
            const float bn[4] = {b4.x, b4.y, b4.z, b4.w};
#pragma unroll
            for (int i = 0; i < 4; i++)
#pragma unroll
                for (int j = 0; j < 4; j++)
                    acc[i][j] += ai[i] * bn[j];
        }
        __syncthreads();
    }

#pragma unroll
    for (int i = 0; i < 4; i++) {
        const size_t off = ((size_t)b * NN + i0 + ty * 4 + i) * DD + n0 + tx * 4;
        *(float4*)&out[off] = make_float4(acc[i][0], acc[i][1], acc[i][2], acc[i][3]);
    }
}

extern "C" void kernel_launch(void* const* d_in, const int* in_sizes, int n_in,
                              void* d_out, int out_size)
{
    const float* hidden = (const float*)d_in[0];
    const int*   adj    = (const int*)d_in[1];
    const float* a0     = (const float*)d_in[2];
    const float* a1     = (const float*)d_in[3];
    const float* a2     = (const float*)d_in[4];
    const float* a3     = (const float*)d_in[5];
    float* out = (float*)d_out;

    dim3 g1(NN / 64, NN / 64, BB);      // (8, 8, 32)
    k_scores<<<g1, 256>>>(hidden, adj, a0, a1, a2, a3);

    k_softmax<<<(BB * NN) / 8, 256>>>();   // 2048 blocks, 8 rows each

    dim3 g3(DD / 64, NN / 64, BB);      // (4, 8, 32)
    k_av<<<g3, 256>>>(hidden, out);
}

// round 3
// speedup vs baseline: 2.4269x; 2.4269x over previous
#include <cuda_runtime.h>
#include <cuda_bf16.h>
#include <cstdint>

#define BB 32
#define NN 512
#define DD 256
#define NEG_INF -9e15f

// ---------------------------------------------------------------------------
// Device scratch (no allocation allowed)
// ---------------------------------------------------------------------------
__device__ float g_e[(size_t)BB * 4 * NN * NN];            // per-head raw scores
__device__ __nv_bfloat16 g_ahi[(size_t)BB * NN * NN];      // alpha hi
__device__ __nv_bfloat16 g_alo[(size_t)BB * NN * NN];      // alpha lo
__device__ __nv_bfloat16 g_whi[(size_t)BB * 4 * NN * DD];  // (h*a_k) hi
__device__ __nv_bfloat16 g_wlo[(size_t)BB * 4 * NN * DD];  // (h*a_k) lo
__device__ __nv_bfloat16 g_bhi[(size_t)BB * NN * DD];      // h hi
__device__ __nv_bfloat16 g_blo[(size_t)BB * NN * DD];      // h lo

// ---------------------------------------------------------------------------
// mma.sync helpers (portable sm_80+ tensor path; tcgen05 is blocked by the
// harness's compute_103 PTX stage)
// ---------------------------------------------------------------------------
__device__ __forceinline__ uint32_t smem_to_u32(const void* p) {
    uint32_t a;
    asm("{ .reg .u64 t; cvta.to.shared.u64 t, %1; cvt.u32.u64 %0, t; }"
        : "=r"(a) : "l"(p));
    return a;
}

__device__ __forceinline__ void ldm_x4(uint32_t* r, uint32_t addr) {
    asm volatile("ldmatrix.sync.aligned.m8n8.x4.shared.b16 {%0,%1,%2,%3}, [%4];"
        : "=r"(r[0]), "=r"(r[1]), "=r"(r[2]), "=r"(r[3]) : "r"(addr));
}
__device__ __forceinline__ void ldm_x4_trans(uint32_t* r, uint32_t addr) {
    asm volatile("ldmatrix.sync.aligned.m8n8.x4.trans.shared.b16 {%0,%1,%2,%3}, [%4];"
        : "=r"(r[0]), "=r"(r[1]), "=r"(r[2]), "=r"(r[3]) : "r"(addr));
}
__device__ __forceinline__ void mma16816(float* c, const uint32_t* a, const uint32_t* b) {
    asm volatile(
        "mma.sync.aligned.m16n8k16.row.col.f32.bf16.bf16.f32 "
        "{%0,%1,%2,%3}, {%4,%5,%6,%7}, {%8,%9}, {%0,%1,%2,%3};"
        : "+f"(c[0]), "+f"(c[1]), "+f"(c[2]), "+f"(c[3])
        : "r"(a[0]), "r"(a[1]), "r"(a[2]), "r"(a[3]), "r"(b[0]), "r"(b[1]));
}

// ---------------------------------------------------------------------------
// K0: split h and w_k = h*a_k into bf16 hi/lo planes
// ---------------------------------------------------------------------------
__device__ __forceinline__ void bf16pair_store(
    __nv_bfloat16* hi, __nv_bfloat16* lo, float4 v)
{
    float f[4] = {v.x, v.y, v.z, v.w};
    __nv_bfloat16 hb[4], lb[4];
#pragma unroll
    for (int j = 0; j < 4; j++) {
        hb[j] = __float2bfloat16_rn(f[j]);
        lb[j] = __float2bfloat16_rn(f[j] - __bfloat162float(hb[j]));
    }
    ((__nv_bfloat162*)hi)[0] = __nv_bfloat162(hb[0], hb[1]);
    ((__nv_bfloat162*)hi)[1] = __nv_bfloat162(hb[2], hb[3]);
    ((__nv_bfloat162*)lo)[0] = __nv_bfloat162(lb[0], lb[1]);
    ((__nv_bfloat162*)lo)[1] = __nv_bfloat162(lb[2], lb[3]);
}

__global__ __launch_bounds__(256) void k_split(
    const float* __restrict__ h,
    const float* __restrict__ a0, const float* __restrict__ a1,
    const float* __restrict__ a2, const float* __restrict__ a3)
{
    const int idx = blockIdx.x * 256 + threadIdx.x;   // over B*N*D/4
    const int row = idx >> 6;
    const int c4  = idx & 63;
    const int d   = c4 * 4;
    const float4 hv = ((const float4*)h)[idx];

    {
        size_t off = (size_t)row * DD + d;
        bf16pair_store(g_bhi + off, g_blo + off, hv);
    }
    const int b = row >> 9, i = row & 511;
    const float* aks[4] = {a0, a1, a2, a3};
#pragma unroll
    for (int k = 0; k < 4; k++) {
        const float4 av = ((const float4*)aks[k])[c4];
        float4 wv = make_float4(hv.x * av.x, hv.y * av.y, hv.z * av.z, hv.w * av.w);
        size_t off = (((size_t)b * 4 + k) * NN + i) * DD + d;
        bf16pair_store(g_whi + off, g_wlo + off, wv);
    }
}

// ---------------------------------------------------------------------------
// K1: tensor scores via mma.sync. CTA = (b, head, 128i x 128j) tile.
// 8 warps in 4(i) x 2(j) grid; warp tile 32i x 64j = 2 m-tiles x 8 n-tiles.
// ---------------------------------------------------------------------------
#define SASTRIDE 72   // 64 bf16 + 8 pad
__global__ __launch_bounds__(256) void k_scores_tc()
{
    __shared__ __nv_bfloat16 sA[128 * SASTRIDE];
    __shared__ __nv_bfloat16 sB[128 * SASTRIDE];

    const int t    = threadIdx.x;
    const int w    = t >> 5;
    const int lane = t & 31;
    const int wi   = w & 3;         // i group (32 rows)
    const int wj   = w >> 2;        // j group (64 cols)
    const int b    = blockIdx.z;
    const int k    = blockIdx.y >> 2;
    const int i0   = (blockIdx.y & 3) * 128;
    const int j0   = blockIdx.x * 128;

    const uint32_t sA_u = smem_to_u32(sA);
    const uint32_t sB_u = smem_to_u32(sB);

    float acc[2][8][4];
#pragma unroll
    for (int m = 0; m < 2; m++)
#pragma unroll
        for (int n = 0; n < 8; n++)
#pragma unroll
            for (int q = 0; q < 4; q++) acc[m][n][q] = 0.f;

    const __nv_bfloat16 *Aw[3], *Bw[3];
    {
        const size_t aoff = (((size_t)b * 4 + k) * NN + i0) * DD;
        const size_t boff = ((size_t)b * NN + j0) * DD;
        Aw[0] = g_whi + aoff; Aw[1] = g_whi + aoff; Aw[2] = g_wlo + aoff;
        Bw[0] = g_bhi + boff; Bw[1] = g_blo + boff; Bw[2] = g_bhi + boff;
    }

    // precomputed ldmatrix smem addresses (byte offsets added per k-step)
    const uint32_t a_row  = wi * 32 + (lane & 15);
    const uint32_t a_colb = (lane >> 4) * 8;
    const uint32_t b_row  = wj * 64 + (lane & 7) + (lane >> 4) * 8;
    const uint32_t b_colb = ((lane >> 3) & 1) * 8;

    for (int s = 0; s < 3; s++) {
        const __nv_bfloat16* Ap = Aw[s];
        const __nv_bfloat16* Bp = Bw[s];
        for (int d0 = 0; d0 < DD; d0 += 64) {
#pragma unroll
            for (int q = t; q < 1024; q += 256) {
                const int r = q >> 3;
                const int c = (q & 7) * 8;
                *(uint4*)&sA[r * SASTRIDE + c] = *(const uint4*)(Ap + (size_t)r * DD + d0 + c);
                *(uint4*)&sB[r * SASTRIDE + c] = *(const uint4*)(Bp + (size_t)r * DD + d0 + c);
            }
            __syncthreads();

#pragma unroll
            for (int ks = 0; ks < 4; ks++) {
                uint32_t afr[2][4];
#pragma unroll
                for (int mt = 0; mt < 2; mt++) {
                    uint32_t addr = sA_u +
                        ((a_row + mt * 16) * SASTRIDE + ks * 16 + a_colb) * 2;
                    ldm_x4(afr[mt], addr);
                }
                uint32_t bfr[8][2];
#pragma unroll
                for (int ntp = 0; ntp < 4; ntp++) {
                    uint32_t r4[4];
                    uint32_t addr = sB_u +
                        ((b_row + ntp * 16) * SASTRIDE + ks * 16 + b_colb) * 2;
                    ldm_x4(r4, addr);
                    bfr[ntp*2][0]   = r4[0]; bfr[ntp*2][1]   = r4[1];
                    bfr[ntp*2+1][0] = r4[2]; bfr[ntp*2+1][1] = r4[3];
                }
#pragma unroll
                for (int mt = 0; mt < 2; mt++)
#pragma unroll
                    for (int nt = 0; nt < 8; nt++)
                        mma16816(acc[mt][nt], afr[mt], bfr[nt]);
            }
            __syncthreads();
        }
    }

    // epilogue -> g_e plane
    const int g  = lane >> 2;
    const int tt = lane & 3;
    float* plane = g_e + (((size_t)b * 4 + k) * NN + i0) * NN + j0;
#pragma unroll
    for (int mt = 0; mt < 2; mt++) {
        const int r0 = wi * 32 + mt * 16 + g;
#pragma unroll
        for (int nt = 0; nt < 8; nt++) {
            const int c0 = wj * 64 + nt * 8 + tt * 2;
            *(float2*)&plane[(size_t)r0 * NN + c0]       = make_float2(acc[mt][nt][0], acc[mt][nt][1]);
            *(float2*)&plane[(size_t)(r0 + 8) * NN + c0] = make_float2(acc[mt][nt][2], acc[mt][nt][3]);
        }
    }
}

// ---------------------------------------------------------------------------
// K2: fused adj-select + leaky-relu + softmax -> bf16 alpha hi/lo
// ---------------------------------------------------------------------------
__global__ __launch_bounds__(256) void k_sel_softmax(const int* __restrict__ adj)
{
    const int w    = threadIdx.x >> 5;
    const int lane = threadIdx.x & 31;
    const size_t row = (size_t)blockIdx.x * 8 + w;
    const int b = (int)(row >> 9);
    const int i = (int)(row & 511);

    const size_t pstride = (size_t)NN * NN;
    const float* e0 = g_e + (((size_t)b * 4 + 0) * NN + i) * NN;
    const float* e1 = e0 + pstride;
    const float* e2 = e1 + pstride;
    const float* e3 = e2 + pstride;
    const int* ar = adj + row * NN;

    float v[16];
#pragma unroll
    for (int q = 0; q < 4; q++) {
        const int idx = q * 32 + lane;
        const float4 x0 = ((const float4*)e0)[idx];
        const float4 x1 = ((const float4*)e1)[idx];
        const float4 x2 = ((const float4*)e2)[idx];
        const float4 x3 = ((const float4*)e3)[idx];
        const int4   c  = ((const int4*)ar)[idx];
        const int   cc[4] = {c.x, c.y, c.z, c.w};
        const float f0[4] = {x0.x, x0.y, x0.z, x0.w};
        const float f1[4] = {x1.x, x1.y, x1.z, x1.w};
        const float f2[4] = {x2.x, x2.y, x2.z, x2.w};
        const float f3[4] = {x3.x, x3.y, x3.z, x3.w};
#pragma unroll
        for (int j = 0; j < 4; j++) {
            const int c1 = cc[j];
            float e;
            if      (c1 == 1) e = f0[j];
            else if (c1 == 2) e = f1[j];
            else if (c1 == 3) e = f2[j];
            else if (c1 == 4) e = f3[j];
            else { v[q * 4 + j] = NEG_INF; continue; }
            v[q * 4 + j] = (e > 0.f) ? e : 0.2f * e;
        }
    }

    float m = v[0];
#pragma unroll
    for (int q = 1; q < 16; q++) m = fmaxf(m, v[q]);
#pragma unroll
    for (int o = 16; o > 0; o >>= 1) m = fmaxf(m, __shfl_xor_sync(0xffffffffu, m, o));

    float sum = 0.f;
#pragma unroll
    for (int q = 0; q < 16; q++) { v[q] = __expf(v[q] - m); sum += v[q]; }
#pragma unroll
    for (int o = 16; o > 0; o >>= 1) sum += __shfl_xor_sync(0xffffffffu, sum, o);

    const float inv = 1.f / sum;
    __nv_bfloat16* ahi = g_ahi + row * NN;
    __nv_bfloat16* alo = g_alo + row * NN;
#pragma unroll
    for (int q = 0; q < 4; q++) {
        const int idx = q * 32 + lane;
        float a4[4];
        __nv_bfloat16 hb[4], lb[4];
#pragma unroll
        for (int j = 0; j < 4; j++) {
            a4[j] = v[q * 4 + j] * inv;
            hb[j] = __float2bfloat16_rn(a4[j]);
            lb[j] = __float2bfloat16_rn(a4[j] - __bfloat162float(hb[j]));
        }
        ((__nv_bfloat162*)(ahi + idx * 4))[0] = __nv_bfloat162(hb[0], hb[1]);
        ((__nv_bfloat162*)(ahi + idx * 4))[1] = __nv_bfloat162(hb[2], hb[3]);
        ((__nv_bfloat162*)(alo + idx * 4))[0] = __nv_bfloat162(lb[0], lb[1]);
        ((__nv_bfloat162*)(alo + idx * 4))[1] = __nv_bfloat162(lb[2], lb[3]);
    }
}

// ---------------------------------------------------------------------------
// K3: out = alpha @ h via mma.sync. CTA = (b, 128i x 128d) tile.
// A = alpha [i, j] (k=j contiguous), B = h [j, d] loaded with ldmatrix.trans.
// ---------------------------------------------------------------------------
#define SBSTRIDE 136  // 128 bf16 + 8 pad
__global__ __launch_bounds__(256) void k_av_tc(float* __restrict__ out)
{
    __shared__ __nv_bfloat16 sA[128 * SASTRIDE];   // alpha chunk 128 x 64
    __shared__ __nv_bfloat16 sB[64 * SBSTRIDE];    // h chunk 64 x 128

    const int t    = threadIdx.x;
    const int w    = t >> 5;
    const int lane = t & 31;
    const int wi   = w & 3;
    const int wj   = w >> 2;
    const int b    = blockIdx.z;
    const int i0   = blockIdx.y * 128;
    const int d0   = blockIdx.x * 128;

    const uint32_t sA_u = smem_to_u32(sA);
    const uint32_t sB_u = smem_to_u32(sB);

    float acc[2][8][4];
#pragma unroll
    for (int m = 0; m < 2; m++)
#pragma unroll
        for (int n = 0; n < 8; n++)
#pragma unroll
            for (int q = 0; q < 4; q++) acc[m][n][q] = 0.f;

    const __nv_bfloat16 *Aw[3], *Bw[3];
    {
        const size_t aoff = ((size_t)b * NN + i0) * NN;
        const size_t boff = (size_t)b * NN * DD;
        Aw[0] = g_ahi + aoff; Aw[1] = g_ahi + aoff; Aw[2] = g_alo + aoff;
        Bw[0] = g_bhi + boff; Bw[1] = g_blo + boff; Bw[2] = g_bhi + boff;
    }

    const uint32_t a_row  = wi * 32 + (lane & 15);
    const uint32_t a_colb = (lane >> 4) * 8;
    const uint32_t bt_row = lane & 15;                 // j within 16-group
    const uint32_t bt_col = wj * 64 + (lane >> 4) * 8; // d base

    for (int s = 0; s < 3; s++) {
        const __nv_bfloat16* Ap = Aw[s];
        const __nv_bfloat16* Bp = Bw[s];
        for (int j0c = 0; j0c < NN; j0c += 64) {
#pragma unroll
            for (int q = t; q < 1024; q += 256) {
                const int r = q >> 3;
                const int c = (q & 7) * 8;
                *(uint4*)&sA[r * SASTRIDE + c] =
                    *(const uint4*)(Ap + (size_t)r * NN + j0c + c);
            }
#pragma unroll
            for (int q = t; q < 1024; q += 256) {
                const int r = q >> 4;
                const int c = (q & 15) * 8;
                *(uint4*)&sB[r * SBSTRIDE + c] =
                    *(const uint4*)(Bp + (size_t)(j0c + r) * DD + d0 + c);
            }
            __syncthreads();

#pragma unroll
            for (int ks = 0; ks < 4; ks++) {
                uint32_t afr[2][4];
#pragma unroll
                for (int mt = 0; mt < 2; mt++) {
                    uint32_t addr = sA_u +
                        ((a_row + mt * 16) * SASTRIDE + ks * 16 + a_colb) * 2;
                    ldm_x4(afr[mt], addr);
                }
                uint32_t bfr[8][2];
#pragma unroll
                for (int ntp = 0; ntp < 4; ntp++) {
                    uint32_t r4[4];
                    uint32_t addr = sB_u +
                        ((ks * 16 + bt_row) * SBSTRIDE + bt_col + ntp * 16) * 2;
                    ldm_x4_trans(r4, addr);
                    bfr[ntp*2][0]   = r4[0]; bfr[ntp*2][1]   = r4[1];
                    bfr[ntp*2+1][0] = r4[2]; bfr[ntp*2+1][1] = r4[3];
                }
#pragma unroll
                for (int mt = 0; mt < 2; mt++)
#pragma unroll
                    for (int nt = 0; nt < 8; nt++)
                        mma16816(acc[mt][nt], afr[mt], bfr[nt]);
            }
            __syncthreads();
        }
    }

    const int g  = lane >> 2;
    const int tt = lane & 3;
    float* obase = out + ((size_t)b * NN + i0) * DD + d0;
#pragma unroll
    for (int mt = 0; mt < 2; mt++) {
        const int r0 = wi * 32 + mt * 16 + g;
#pragma unroll
        for (int nt = 0; nt < 8; nt++) {
            const int c0 = wj * 64 + nt * 8 + tt * 2;
            *(float2*)&obase[(size_t)r0 * DD + c0]       = make_float2(acc[mt][nt][0], acc[mt][nt][1]);
            *(float2*)&obase[(size_t)(r0 + 8) * DD + c0] = make_float2(acc[mt][nt][2], acc[mt][nt][3]);
        }
    }
}

// ---------------------------------------------------------------------------
extern "C" void kernel_launch(void* const* d_in, const int* in_sizes, int n_in,
                              void* d_out, int out_size)
{
    const float* hidden = (const float*)d_in[0];
    const int*   adj    = (const int*)d_in[1];
    const float* a0     = (const float*)d_in[2];
    const float* a1     = (const float*)d_in[3];
    const float* a2     = (const float*)d_in[4];
    const float* a3     = (const float*)d_in[5];
    float* out = (float*)d_out;

    k_split<<<(BB * NN * DD / 4) / 256, 256>>>(hidden, a0, a1, a2, a3);

    dim3 g1(NN / 128, 16, BB);   // (4 j-tiles, 4 heads x 4 i-tiles, 32 b)
    k_scores_tc<<<g1, 256>>>();

    k_sel_softmax<<<(BB * NN) / 8, 256>>>(adj);

    dim3 g3(DD / 128, NN / 128, BB);  // (2, 4, 32)
    k_av_tc<<<g3, 256>>>(out);
}

// round 4
// speedup vs baseline: 2.6668x; 1.0988x over previous
#include <cuda_runtime.h>
#include <cuda_bf16.h>
#include <cstdint>

#define BB 32
#define NN 512
#define DD 256
#define NEG_INF -9e15f

// ---------------------------------------------------------------------------
// Device scratch (no allocation allowed)
// ---------------------------------------------------------------------------
__device__ float g_e[(size_t)BB * 4 * NN * NN];            // per-head raw scores
__device__ __nv_bfloat16 g_ahi[(size_t)BB * NN * NN];      // alpha hi
__device__ __nv_bfloat16 g_alo[(size_t)BB * NN * NN];      // alpha lo
__device__ __nv_bfloat16 g_whi[(size_t)BB * 4 * NN * DD];  // (h*a_k) hi
__device__ __nv_bfloat16 g_wlo[(size_t)BB * 4 * NN * DD];  // (h*a_k) lo
__device__ __nv_bfloat16 g_bhi[(size_t)BB * NN * DD];      // h hi
__device__ __nv_bfloat16 g_blo[(size_t)BB * NN * DD];      // h lo

// ---------------------------------------------------------------------------
// mma.sync / cp.async helpers (portable sm_80+ path; tcgen05 blocked by the
// harness's compute_103 PTX stage)
// ---------------------------------------------------------------------------
__device__ __forceinline__ uint32_t smem_to_u32(const void* p) {
    uint32_t a;
    asm("{ .reg .u64 t; cvta.to.shared.u64 t, %1; cvt.u32.u64 %0, t; }"
        : "=r"(a) : "l"(p));
    return a;
}
__device__ __forceinline__ void ldm_x4(uint32_t* r, uint32_t addr) {
    asm volatile("ldmatrix.sync.aligned.m8n8.x4.shared.b16 {%0,%1,%2,%3}, [%4];"
        : "=r"(r[0]), "=r"(r[1]), "=r"(r[2]), "=r"(r[3]) : "r"(addr));
}
__device__ __forceinline__ void ldm_x4_trans(uint32_t* r, uint32_t addr) {
    asm volatile("ldmatrix.sync.aligned.m8n8.x4.trans.shared.b16 {%0,%1,%2,%3}, [%4];"
        : "=r"(r[0]), "=r"(r[1]), "=r"(r[2]), "=r"(r[3]) : "r"(addr));
}
__device__ __forceinline__ void mma16816(float* c, const uint32_t* a, const uint32_t* b) {
    asm volatile(
        "mma.sync.aligned.m16n8k16.row.col.f32.bf16.bf16.f32 "
        "{%0,%1,%2,%3}, {%4,%5,%6,%7}, {%8,%9}, {%0,%1,%2,%3};"
        : "+f"(c[0]), "+f"(c[1]), "+f"(c[2]), "+f"(c[3])
        : "r"(a[0]), "r"(a[1]), "r"(a[2]), "r"(a[3]), "r"(b[0]), "r"(b[1]));
}
__device__ __forceinline__ void cp16(uint32_t dst, const void* src) {
    asm volatile("cp.async.cg.shared.global [%0], [%1], 16;" :: "r"(dst), "l"(src));
}
#define CP_COMMIT() asm volatile("cp.async.commit_group;" ::: "memory")
#define CP_WAIT(n)  asm volatile("cp.async.wait_group %0;" :: "n"(n) : "memory")

// ---------------------------------------------------------------------------
// K0: split h and w_k = h*a_k into bf16 hi/lo planes
// ---------------------------------------------------------------------------
__device__ __forceinline__ void bf16pair_store(
    __nv_bfloat16* hi, __nv_bfloat16* lo, float4 v)
{
    float f[4] = {v.x, v.y, v.z, v.w};
    __nv_bfloat16 hb[4], lb[4];
#pragma unroll
    for (int j = 0; j < 4; j++) {
        hb[j] = __float2bfloat16_rn(f[j]);
        lb[j] = __float2bfloat16_rn(f[j] - __bfloat162float(hb[j]));
    }
    ((__nv_bfloat162*)hi)[0] = __nv_bfloat162(hb[0], hb[1]);
    ((__nv_bfloat162*)hi)[1] = __nv_bfloat162(hb[2], hb[3]);
    ((__nv_bfloat162*)lo)[0] = __nv_bfloat162(lb[0], lb[1]);
    ((__nv_bfloat162*)lo)[1] = __nv_bfloat162(lb[2], lb[3]);
}

__global__ __launch_bounds__(256) void k_split(
    const float* __restrict__ h,
    const float* __restrict__ a0, const float* __restrict__ a1,
    const float* __restrict__ a2, const float* __restrict__ a3)
{
    const int idx = blockIdx.x * 256 + threadIdx.x;
    const int row = idx >> 6;
    const int c4  = idx & 63;
    const int d   = c4 * 4;
    const float4 hv = ((const float4*)h)[idx];

    {
        size_t off = (size_t)row * DD + d;
        bf16pair_store(g_bhi + off, g_blo + off, hv);
    }
    const int b = row >> 9, i = row & 511;
    const float* aks[4] = {a0, a1, a2, a3};
#pragma unroll
    for (int k = 0; k < 4; k++) {
        const float4 av = ((const float4*)aks[k])[c4];
        float4 wv = make_float4(hv.x * av.x, hv.y * av.y, hv.z * av.z, hv.w * av.w);
        size_t off = (((size_t)b * 4 + k) * NN + i) * DD + d;
        bf16pair_store(g_whi + off, g_wlo + off, wv);
    }
}

// ---------------------------------------------------------------------------
// K1: tensor scores, 2-stage cp.async pipeline, all 4 planes per k-chunk.
// CTA = (b, head, 128i x 128j). 8 warps 4(i) x 2(j), warp tile 32 x 64.
// chunk = 32 (2 k-steps). Strides padded for conflict-free ldmatrix.
// ---------------------------------------------------------------------------
#define SAS 40                       // 32 bf16 + 8 pad (80B rows)
#define S_PLANE (128 * SAS)          // bf16 elems per plane tile
#define S_STAGE (4 * S_PLANE)        // whi, wlo, bhi, blo
#define S_SMEM_BYTES (2 * S_STAGE * 2)

__global__ void __launch_bounds__(256, 2) k_scores_tc()
{
    extern __shared__ __nv_bfloat16 sm[];

    const int t    = threadIdx.x;
    const int w    = t >> 5;
    const int lane = t & 31;
    const int wi   = w & 3;
    const int wj   = w >> 2;
    const int b    = blockIdx.z;
    const int k    = blockIdx.y >> 2;
    const int i0   = (blockIdx.y & 3) * 128;
    const int j0   = blockIdx.x * 128;

    const uint32_t smu = smem_to_u32(sm);

    const size_t aoff = (((size_t)b * 4 + k) * NN + i0) * DD;
    const size_t boff = ((size_t)b * NN + j0) * DD;
    const __nv_bfloat16* gA0 = g_whi + aoff;
    const __nv_bfloat16* gA1 = g_wlo + aoff;
    const __nv_bfloat16* gB0 = g_bhi + boff;
    const __nv_bfloat16* gB1 = g_blo + boff;

    float acc[2][8][4];
#pragma unroll
    for (int m = 0; m < 2; m++)
#pragma unroll
        for (int n = 0; n < 8; n++)
#pragma unroll
            for (int q = 0; q < 4; q++) acc[m][n][q] = 0.f;

    const uint32_t a_row  = wi * 32 + (lane & 15);
    const uint32_t a_colb = (lane >> 4) * 8;
    const uint32_t b_row  = wj * 64 + (lane & 7) + (lane >> 4) * 8;
    const uint32_t b_colb = ((lane >> 3) & 1) * 8;

    auto load_stage = [&](int st, int d0) {
        const uint32_t s0 = smu + (uint32_t)(st * S_STAGE) * 2;
#pragma unroll
        for (int q = t; q < 512; q += 256) {
            const int r = q >> 2;
            const int c = (q & 3) * 8;
            const uint32_t so = (uint32_t)(r * SAS + c) * 2;
            const size_t go = (size_t)r * DD + d0 + c;
            cp16(s0 + 0 * S_PLANE * 2 + so, gA0 + go);
            cp16(s0 + 1 * S_PLANE * 2 + so, gA1 + go);
            cp16(s0 + 2 * S_PLANE * 2 + so, gB0 + go);
            cp16(s0 + 3 * S_PLANE * 2 + so, gB1 + go);
        }
    };

    load_stage(0, 0);
    CP_COMMIT();

    const int NCH = DD / 32;   // 8 chunks
    for (int c = 0; c < NCH; c++) {
        if (c + 1 < NCH) {
            load_stage((c + 1) & 1, (c + 1) * 32);
            CP_COMMIT();
            CP_WAIT(1);
        } else {
            CP_WAIT(0);
        }
        __syncthreads();

        const uint32_t s0   = smu + (uint32_t)((c & 1) * S_STAGE) * 2;
        const uint32_t sWhi = s0;
        const uint32_t sWlo = s0 + 1 * S_PLANE * 2;
        const uint32_t sBhi = s0 + 2 * S_PLANE * 2;
        const uint32_t sBlo = s0 + 3 * S_PLANE * 2;

#pragma unroll
        for (int ks = 0; ks < 2; ks++) {
            uint32_t ahi[2][4], alo[2][4];
#pragma unroll
            for (int mt = 0; mt < 2; mt++) {
                const uint32_t off = ((a_row + mt * 16) * SAS + ks * 16 + a_colb) * 2;
                ldm_x4(ahi[mt], sWhi + off);
                ldm_x4(alo[mt], sWlo + off);
            }
#pragma unroll
            for (int ntp = 0; ntp < 4; ntp++) {
                uint32_t bh[4], bl[4];
                const uint32_t off = ((b_row + ntp * 16) * SAS + ks * 16 + b_colb) * 2;
                ldm_x4(bh, sBhi + off);
                ldm_x4(bl, sBlo + off);
#pragma unroll
                for (int mt = 0; mt < 2; mt++) {
                    mma16816(acc[mt][ntp*2],   ahi[mt], bh);
                    mma16816(acc[mt][ntp*2+1], ahi[mt], bh + 2);
                    mma16816(acc[mt][ntp*2],   ahi[mt], bl);
                    mma16816(acc[mt][ntp*2+1], ahi[mt], bl + 2);
                    mma16816(acc[mt][ntp*2],   alo[mt], bh);
                    mma16816(acc[mt][ntp*2+1], alo[mt], bh + 2);
                }
            }
        }
        __syncthreads();
    }

    // epilogue -> g_e plane
    const int g  = lane >> 2;
    const int tt = lane & 3;
    float* plane = g_e + (((size_t)b * 4 + k) * NN + i0) * NN + j0;
#pragma unroll
    for (int mt = 0; mt < 2; mt++) {
        const int r0 = wi * 32 + mt * 16 + g;
#pragma unroll
        for (int nt = 0; nt < 8; nt++) {
            const int c0 = wj * 64 + nt * 8 + tt * 2;
            *(float2*)&plane[(size_t)r0 * NN + c0]       = make_float2(acc[mt][nt][0], acc[mt][nt][1]);
            *(float2*)&plane[(size_t)(r0 + 8) * NN + c0] = make_float2(acc[mt][nt][2], acc[mt][nt][3]);
        }
    }
}

// ---------------------------------------------------------------------------
// K2: fused adj-select + leaky-relu + softmax -> bf16 alpha hi/lo
// ---------------------------------------------------------------------------
__global__ __launch_bounds__(256) void k_sel_softmax(const int* __restrict__ adj)
{
    const int w    = threadIdx.x >> 5;
    const int lane = threadIdx.x & 31;
    const size_t row = (size_t)blockIdx.x * 8 + w;
    const int b = (int)(row >> 9);
    const int i = (int)(row & 511);

    const size_t pstride = (size_t)NN * NN;
    const float* e0 = g_e + (((size_t)b * 4 + 0) * NN + i) * NN;
    const float* e1 = e0 + pstride;
    const float* e2 = e1 + pstride;
    const float* e3 = e2 + pstride;
    const int* ar = adj + row * NN;

    float v[16];
#pragma unroll
    for (int q = 0; q < 4; q++) {
        const int idx = q * 32 + lane;
        const float4 x0 = ((const float4*)e0)[idx];
        const float4 x1 = ((const float4*)e1)[idx];
        const float4 x2 = ((const float4*)e2)[idx];
        const float4 x3 = ((const float4*)e3)[idx];
        const int4   c  = ((const int4*)ar)[idx];
        const int   cc[4] = {c.x, c.y, c.z, c.w};
        const float f0[4] = {x0.x, x0.y, x0.z, x0.w};
        const float f1[4] = {x1.x, x1.y, x1.z, x1.w};
        const float f2[4] = {x2.x, x2.y, x2.z, x2.w};
        const float f3[4] = {x3.x, x3.y, x3.z, x3.w};
#pragma unroll
        for (int j = 0; j < 4; j++) {
            const int c1 = cc[j];
            float e;
            if      (c1 == 1) e = f0[j];
            else if (c1 == 2) e = f1[j];
            else if (c1 == 3) e = f2[j];
            else if (c1 == 4) e = f3[j];
            else { v[q * 4 + j] = NEG_INF; continue; }
            v[q * 4 + j] = (e > 0.f) ? e : 0.2f * e;
        }
    }

    float m = v[0];
#pragma unroll
    for (int q = 1; q < 16; q++) m = fmaxf(m, v[q]);
#pragma unroll
    for (int o = 16; o > 0; o >>= 1) m = fmaxf(m, __shfl_xor_sync(0xffffffffu, m, o));

    float sum = 0.f;
#pragma unroll
    for (int q = 0; q < 16; q++) { v[q] = __expf(v[q] - m); sum += v[q]; }
#pragma unroll
    for (int o = 16; o > 0; o >>= 1) sum += __shfl_xor_sync(0xffffffffu, sum, o);

    const float inv = 1.f / sum;
    __nv_bfloat16* ahi = g_ahi + row * NN;
    __nv_bfloat16* alo = g_alo + row * NN;
#pragma unroll
    for (int q = 0; q < 4; q++) {
        const int idx = q * 32 + lane;
        float a4[4];
        __nv_bfloat16 hb[4], lb[4];
#pragma unroll
        for (int j = 0; j < 4; j++) {
            a4[j] = v[q * 4 + j] * inv;
            hb[j] = __float2bfloat16_rn(a4[j]);
            lb[j] = __float2bfloat16_rn(a4[j] - __bfloat162float(hb[j]));
        }
        ((__nv_bfloat162*)(ahi + idx * 4))[0] = __nv_bfloat162(hb[0], hb[1]);
        ((__nv_bfloat162*)(ahi + idx * 4))[1] = __nv_bfloat162(hb[2], hb[3]);
        ((__nv_bfloat162*)(alo + idx * 4))[0] = __nv_bfloat162(lb[0], lb[1]);
        ((__nv_bfloat162*)(alo + idx * 4))[1] = __nv_bfloat162(lb[2], lb[3]);
    }
}

// ---------------------------------------------------------------------------
// K3: out = alpha @ h, 2-stage cp.async pipeline.
// CTA = (b, 128i x 128d); A = alpha (j contiguous), B = h (d contiguous, trans)
// ---------------------------------------------------------------------------
#define VBS 136                        // 128 bf16 + 8 pad (272B rows)
#define V_APLANE (128 * SAS)           // 128 x 32 (+pad)
#define V_BPLANE (32 * VBS)            // 32 x 128 (+pad)
#define V_STAGE  (2 * V_APLANE + 2 * V_BPLANE)
#define V_SMEM_BYTES (2 * V_STAGE * 2)

__global__ void __launch_bounds__(256, 2) k_av_tc(float* __restrict__ out)
{
    extern __shared__ __nv_bfloat16 sm[];

    const int t    = threadIdx.x;
    const int w    = t >> 5;
    const int lane = t & 31;
    const int wi   = w & 3;
    const int wj   = w >> 2;
    const int b    = blockIdx.z;
    const int i0   = blockIdx.y * 128;
    const int d0   = blockIdx.x * 128;

    const uint32_t smu = smem_to_u32(sm);

    const size_t aoff = ((size_t)b * NN + i0) * NN;
    const size_t boff = (size_t)b * NN * DD;
    const __nv_bfloat16* gA0 = g_ahi + aoff;
    const __nv_bfloat16* gA1 = g_alo + aoff;
    const __nv_bfloat16* gB0 = g_bhi + boff;
    const __nv_bfloat16* gB1 = g_blo + boff;

    float acc[2][8][4];
#pragma unroll
    for (int m = 0; m < 2; m++)
#pragma unroll
        for (int n = 0; n < 8; n++)
#pragma unroll
            for (int q = 0; q < 4; q++) acc[m][n][q] = 0.f;

    const uint32_t a_row  = wi * 32 + (lane & 15);
    const uint32_t a_colb = (lane >> 4) * 8;
    const uint32_t bt_row = lane & 15;
    const uint32_t bt_col = wj * 64 + (lane >> 4) * 8;

    auto load_stage = [&](int st, int j0c) {
        const uint32_t s0 = smu + (uint32_t)(st * V_STAGE) * 2;
#pragma unroll
        for (int q = t; q < 512; q += 256) {
            const int r = q >> 2;
            const int c = (q & 3) * 8;
            const uint32_t so = (uint32_t)(r * SAS + c) * 2;
            const size_t go = (size_t)r * NN + j0c + c;
            cp16(s0 + so, gA0 + go);
            cp16(s0 + V_APLANE * 2 + so, gA1 + go);
        }
#pragma unroll
        for (int q = t; q < 512; q += 256) {
            const int r = q >> 4;
            const int c = (q & 15) * 8;
            const uint32_t so = (uint32_t)(r * VBS + c) * 2;
            const size_t go = (size_t)(j0c + r) * DD + d0 + c;
            cp16(s0 + 2 * V_APLANE * 2 + so, gB0 + go);
            cp16(s0 + 2 * V_APLANE * 2 + V_BPLANE * 2 + so, gB1 + go);
        }
    };

    load_stage(0, 0);
    CP_COMMIT();

    const int NCH = NN / 32;   // 16 chunks
    for (int c = 0; c < NCH; c++) {
        if (c + 1 < NCH) {
            load_stage((c + 1) & 1, (c + 1) * 32);
            CP_COMMIT();
            CP_WAIT(1);
        } else {
            CP_WAIT(0);
        }
        __syncthreads();

        const uint32_t s0   = smu + (uint32_t)((c & 1) * V_STAGE) * 2;
        const uint32_t sAhi = s0;
        const uint32_t sAlo = s0 + V_APLANE * 2;
        const uint32_t sBhi = s0 + 2 * V_APLANE * 2;
        const uint32_t sBlo = sBhi + V_BPLANE * 2;

#pragma unroll
        for (int ks = 0; ks < 2; ks++) {
            uint32_t ahi[2][4], alo[2][4];
#pragma unroll
            for (int mt = 0; mt < 2; mt++) {
                const uint32_t off = ((a_row + mt * 16) * SAS + ks * 16 + a_colb) * 2;
                ldm_x4(ahi[mt], sAhi + off);
                ldm_x4(alo[mt], sAlo + off);
            }
#pragma unroll
            for (int ntp = 0; ntp < 4; ntp++) {
                uint32_t bh[4], bl[4];
                const uint32_t off = ((ks * 16 + bt_row) * VBS + bt_col + ntp * 16) * 2;
                ldm_x4_trans(bh, sBhi + off);
                ldm_x4_trans(bl, sBlo + off);
#pragma unroll
                for (int mt = 0; mt < 2; mt++) {
                    mma16816(acc[mt][ntp*2],   ahi[mt], bh);
                    mma16816(acc[mt][ntp*2+1], ahi[mt], bh + 2);
                    mma16816(acc[mt][ntp*2],   ahi[mt], bl);
                    mma16816(acc[mt][ntp*2+1], ahi[mt], bl + 2);
                    mma16816(acc[mt][ntp*2],   alo[mt], bh);
                    mma16816(acc[mt][ntp*2+1], alo[mt], bh + 2);
                }
            }
        }
        __syncthreads();
    }

    const int g  = lane >> 2;
    const int tt = lane & 3;
    float* obase = out + ((size_t)b * NN + i0) * DD + d0;
#pragma unroll
    for (int mt = 0; mt < 2; mt++) {
        const int r0 = wi * 32 + mt * 16 + g;
#pragma unroll
        for (int nt = 0; nt < 8; nt++) {
            const int c0 = wj * 64 + nt * 8 + tt * 2;
            *(float2*)&obase[(size_t)r0 * DD + c0]       = make_float2(acc[mt][nt][0], acc[mt][nt][1]);
            *(float2*)&obase[(size_t)(r0 + 8) * DD + c0] = make_float2(acc[mt][nt][2], acc[mt][nt][3]);
        }
    }
}

// ---------------------------------------------------------------------------
extern "C" void kernel_launch(void* const* d_in, const int* in_sizes, int n_in,
                              void* d_out, int out_size)
{
    const float* hidden = (const float*)d_in[0];
    const int*   adj    = (const int*)d_in[1];
    const float* a0     = (const float*)d_in[2];
    const float* a1     = (const float*)d_in[3];
    const float* a2     = (const float*)d_in[4];
    const float* a3     = (const float*)d_in[5];
    float* out = (float*)d_out;

    cudaFuncSetAttribute(k_scores_tc,
        cudaFuncAttributeMaxDynamicSharedMemorySize, S_SMEM_BYTES);
    cudaFuncSetAttribute(k_av_tc,
        cudaFuncAttributeMaxDynamicSharedMemorySize, V_SMEM_BYTES);

    k_split<<<(BB * NN * DD / 4) / 256, 256>>>(hidden, a0, a1, a2, a3);

    dim3 g1(NN / 128, 16, BB);
    k_scores_tc<<<g1, 256, S_SMEM_BYTES>>>();

    k_sel_softmax<<<(BB * NN) / 8, 256>>>(adj);

    dim3 g3(DD / 128, NN / 128, BB);
    k_av_tc<<<g3, 256, V_SMEM_BYTES>>>(out);
}